// round 15
// baseline (speedup 1.0000x reference)
#include <cuda_runtime.h>

#define B_ 4
#define C_ 8
#define F_ 512
#define T_ 1000

#define SPEC_N 16384000ll   // B*C*F*T
#define NBF    2048         // B*F
#define TILE   200          // T tile; 1000 = 5 * 200; 200 % 4 == 0

// triangle pair index for r <= e
#define IDX(r, e) ((r) * 8 + (e) - ((r) * ((r) + 1)) / 2)   // 0..35

// ---------------- helpers (proven) ----------------
__device__ __forceinline__ float gldf(const float* p, long long i, long long cap) {
    return (i >= 0 && i < cap) ? p[i] : 0.0f;
}
__device__ __forceinline__ float4 gld4(const float* p, long long i, long long cap) {
    if (i >= 0 && i + 3 < cap && ((i & 3) == 0))
        return *(const float4*)(p + i);
    return make_float4(gldf(p, i, cap), gldf(p, i + 1, cap),
                       gldf(p, i + 2, cap), gldf(p, i + 3, cap));
}
__device__ __forceinline__ float2 cmul(float2 a, float2 b) {
    return make_float2(fmaf(a.x, b.x, -a.y * b.y), fmaf(a.x, b.y, a.y * b.x));
}
__device__ __forceinline__ float2 crecip(float2 a) {
    float inv = 1.0f / fmaf(a.x, a.x, a.y * a.y);
    return make_float2(a.x * inv, -a.y * inv);
}
__device__ __forceinline__ float2 wred2(float2 v) {
    #pragma unroll
    for (int o = 16; o; o >>= 1) {
        v.x += __shfl_xor_sync(0xffffffffu, v.x, o);
        v.y += __shfl_xor_sync(0xffffffffu, v.y, o);
    }
    return v;
}

// ---- fused kernel: one block per (b,f); 256 threads = 8 warps ----
__global__ void __launch_bounds__(256)
kf(const float* __restrict__ re, const float* __restrict__ im,
   const float* __restrict__ ms, const float* __restrict__ mn,
   float* __restrict__ outf,
   long long caps, long long capm, long long capoutf)
{
    __shared__ float2 sRe[8][TILE / 2];   // 6400 B
    __shared__ float2 sIm[8][TILE / 2];   // 6400 B
    __shared__ float2 sMs[TILE / 2];      //  800 B
    __shared__ float2 sMn[TILE / 2];      //  800 B
    __shared__ float  sPsd[36 * 4];       //  576 B   [pair][S.re,S.im,N.re,N.im]
    __shared__ float2 sG[64];             //  512 B   G[m][c] = conj(W[c][m])
    __shared__ float  sMsum[2];

    const int bf   = blockIdx.x;
    const int b    = bf >> 9, f = bf & 511;
    const int tid  = threadIdx.x;
    const int warp = tid >> 5;
    const int lane = tid & 31;
    const int r    = warp;                // this warp's PSD row

    int xb[8];
    #pragma unroll
    for (int c = 0; c < 8; c++)
        xb[c] = ((b * C_ + c) * F_ + f) * T_;
    const int mb = bf * T_;

    // ---------- Phase A: masked PSD via smem tiles ----------
    float a[8][4];
    #pragma unroll
    for (int e = 0; e < 8; e++) { a[e][0] = a[e][1] = a[e][2] = a[e][3] = 0.f; }
    float ss = 0.f, sn = 0.f;

    for (int t0 = 0; t0 < T_; t0 += TILE) {
        __syncthreads();   // previous tile fully consumed
        // cooperative load: 8 rows x (TILE/4) float4 groups, re and im
        for (int k = tid; k < 8 * (TILE / 4); k += 256) {
            const int row = k / (TILE / 4);
            const int g   = k % (TILE / 4);
            const long long idx = (long long)xb[row] + t0 + g * 4;
            float4 vr = gld4(re, idx, caps);
            float4 vi = gld4(im, idx, caps);
            sRe[row][g * 2]     = make_float2(vr.x, vr.y);
            sRe[row][g * 2 + 1] = make_float2(vr.z, vr.w);
            sIm[row][g * 2]     = make_float2(vi.x, vi.y);
            sIm[row][g * 2 + 1] = make_float2(vi.z, vi.w);
        }
        for (int k = tid; k < TILE / 4; k += 256) {
            const long long idx = (long long)mb + t0 + k * 4;
            float4 v0 = gld4(ms, idx, capm);
            float4 v1 = gld4(mn, idx, capm);
            sMs[k * 2]     = make_float2(v0.x, v0.y);
            sMs[k * 2 + 1] = make_float2(v0.z, v0.w);
            sMn[k * 2]     = make_float2(v1.x, v1.y);
            sMn[k * 2 + 1] = make_float2(v1.z, v1.w);
        }
        __syncthreads();   // tile ready

        for (int u = lane; u < TILE / 2; u += 32) {
            const float2 m0 = sMs[u], m1 = sMn[u];
            if (warp == 0) { ss += m0.x + m0.y; sn += m1.x + m1.y; }
            const float2 xr = sRe[r][u], xi = sIm[r][u];
            #pragma unroll
            for (int e = 0; e < 8; e++) {
                const float2 yr = sRe[e][u], yi = sIm[e][u];
                // t even lane of the pair
                float cr = fmaf(xr.x, yr.x,  xi.x * yi.x);   // x_r * conj(x_e)
                float ci = fmaf(xi.x, yr.x, -xr.x * yi.x);
                a[e][0] = fmaf(m0.x, cr, a[e][0]);
                a[e][1] = fmaf(m0.x, ci, a[e][1]);
                a[e][2] = fmaf(m1.x, cr, a[e][2]);
                a[e][3] = fmaf(m1.x, ci, a[e][3]);
                // t odd lane of the pair
                cr = fmaf(xr.y, yr.y,  xi.y * yi.y);
                ci = fmaf(xi.y, yr.y, -xr.y * yi.y);
                a[e][0] = fmaf(m0.y, cr, a[e][0]);
                a[e][1] = fmaf(m0.y, ci, a[e][1]);
                a[e][2] = fmaf(m1.y, cr, a[e][2]);
                a[e][3] = fmaf(m1.y, ci, a[e][3]);
            }
        }
    }

    // warp-reduce rows; warp r stores its upper-triangle entries (e >= r)
    #pragma unroll
    for (int e = 0; e < 8; e++) {
        float2 vS = wred2(make_float2(a[e][0], a[e][1]));
        float2 vN = wred2(make_float2(a[e][2], a[e][3]));
        if (lane == 0 && e >= r) {
            const int p = IDX(r, e) * 4;
            sPsd[p + 0] = vS.x; sPsd[p + 1] = vS.y;
            sPsd[p + 2] = vN.x; sPsd[p + 3] = vN.y;
        }
    }
    if (warp == 0) {
        float2 mm = wred2(make_float2(ss, sn));
        if (lane == 0) { sMsum[0] = mm.x; sMsum[1] = mm.y; }
    }
    __syncthreads();

    // ---------- Phase B: warp-0 Gauss-Jordan (proven kS body on smem) ----------
    if (warp == 0) {
        const float invS = 1.0f / (sMsum[0] + 1e-10f);
        const float invN = 1.0f / (sMsum[1] + 1e-10f);

        float trN = 0.f;
        #pragma unroll
        for (int i = 0; i < 8; i++)
            trN += sPsd[IDX(i, i) * 4 + 2];
        trN *= invN;
        const float dreg = 1e-6f * trN + 1e-8f;

        const int jc  = lane & 7;
        const int isB = (lane >> 3) & 1;      // lanes 8..15 own B (psd_s) columns
        const float sc = isB ? invS : invN;
        const int qo = isB ? 0 : 2;

        float2 col[8];
        #pragma unroll
        for (int i = 0; i < 8; i++) {
            const int rr = i < jc ? i : jc;
            const int ee = i < jc ? jc : i;
            const int p  = IDX(rr, ee) * 4 + qo;
            float vr = sPsd[p] * sc;
            float vi = sPsd[p + 1] * sc;
            if (i > jc) vi = -vi;             // Hermitian reconstruction
            col[i] = make_float2(vr, vi);
            if (!isB && i == jc) col[i].x += dreg;
        }

        #pragma unroll
        for (int k = 0; k < 8; k++) {
            float2 piv;
            piv.x = __shfl_sync(0xffffffffu, col[k].x, k);
            piv.y = __shfl_sync(0xffffffffu, col[k].y, k);
            float2 pinv = crecip(piv);
            col[k] = cmul(col[k], pinv);
            #pragma unroll
            for (int i = 0; i < 8; i++) {
                if (i == k) continue;
                float2 fct;
                fct.x = __shfl_sync(0xffffffffu, col[i].x, k);
                fct.y = __shfl_sync(0xffffffffu, col[i].y, k);
                float2 t2 = cmul(fct, col[k]);
                col[i].x -= t2.x; col[i].y -= t2.y;
            }
        }

        float2 dg = make_float2(0.f, 0.f);
        #pragma unroll
        for (int i = 0; i < 8; i++)
            if (lane == 8 + i) dg = col[i];
        dg = wred2(dg);
        float2 cd = make_float2(1.0f + dg.x, -dg.y);   // conj(beta + tr(X))
        float2 E  = crecip(cd);

        if (lane >= 8 && lane < 16) {
            const int m = lane - 8;
            #pragma unroll
            for (int c = 0; c < 8; c++) {
                float2 xc = make_float2(col[c].x, -col[c].y);
                sG[m * 8 + c] = cmul(xc, E);   // G[m][c] = conj(W[c][m])
            }
        }
    }
    __syncthreads();

    // ---------- Phase C: apply (proven k2 body). PLANAR (2,B,C,F,T) out ----------
    for (int t = tid; t < T_; t += 256) {
        float xr[8], xi[8];
        #pragma unroll
        for (int c = 0; c < 8; c++) {
            xr[c] = gldf(re, (long long)xb[c] + t, caps);
            xi[c] = gldf(im, (long long)xb[c] + t, caps);
        }
        #pragma unroll
        for (int m = 0; m < 8; m++) {
            float ar = 0.f, ai = 0.f;
            #pragma unroll
            for (int c = 0; c < 8; c++) {
                float2 g = sG[m * 8 + c];
                ar = fmaf(g.x, xr[c], ar);
                ar = fmaf(-g.y, xi[c], ar);
                ai = fmaf(g.x, xi[c], ai);
                ai = fmaf(g.y, xr[c], ai);
            }
            const long long oc = (long long)xb[m] + t;
            if (oc >= 0 && oc < capoutf)                   outf[oc] = ar;
            if (SPEC_N + oc >= 0 && SPEC_N + oc < capoutf) outf[SPEC_N + oc] = ai;
        }
    }
}

extern "C" void kernel_launch(void* const* d_in, const int* in_sizes, int n_in,
                              void* d_out, int out_size) {
    if (n_in < 4 || !d_out) return;

    const float* re  = (const float*)d_in[0];
    const float* im  = (const float*)d_in[1];
    const float* mks = (const float*)d_in[2];
    const float* mkn = (const float*)d_in[3];
    long long cap_re = (long long)in_sizes[0];
    long long cap_im = (long long)in_sizes[1];
    long long caps   = cap_re < cap_im ? cap_re : cap_im;
    long long cm0 = (long long)in_sizes[2];
    long long cm1 = (long long)in_sizes[3];
    long long capm = cm0 < cm1 ? cm0 : cm1;
    long long capoutf = (long long)out_size;   // float32 element count (confirmed)

    kf<<<NBF, 256>>>(re, im, mks, mkn, (float*)d_out, caps, capm, capoutf);
}

// round 16
// speedup vs baseline: 1.4244x; 1.4244x over previous
#include <cuda_runtime.h>

#define B_ 4
#define C_ 8
#define F_ 512
#define T_ 1000

#define SPEC_N 16384000ll   // B*C*F*T
#define NBF    2048         // B*F
#define ROWSTRIDE 512000    // F_*T_

// triangle pair index for r <= e
#define IDX(r, e) ((r) * 8 + (e) - ((r) * ((r) + 1)) / 2)   // 0..35

// -------- device scratch --------
// reduced PSD partials: [bf][p36][q4][half2]  q: 0=S.re 1=S.im 2=N.re 3=N.im
__device__ __align__(16) float d_part2[(size_t)NBF * 288];
__device__ float d_msum[NBF * 4];                       // [bf][half][s/n]
__device__ __align__(16) float d_G[(size_t)NBF * 128];  // [bf][m][c][2] : conj(W[c][m])

// ---------------- helpers ----------------
__device__ __forceinline__ float gldf(const float* p, long long i, long long cap) {
    return (i >= 0 && i < cap) ? p[i] : 0.0f;
}
__device__ __forceinline__ float2 gld2(const float* p, long long i, long long cap) {
    if (i >= 0 && i + 1 < cap && ((i & 1) == 0))
        return *(const float2*)(p + i);
    return make_float2(gldf(p, i, cap), gldf(p, i + 1, cap));
}
__device__ __forceinline__ float4 gld4(const float* p, long long i, long long cap) {
    if (i >= 0 && i + 3 < cap && ((i & 3) == 0))
        return *(const float4*)(p + i);
    return make_float4(gldf(p, i, cap), gldf(p, i + 1, cap),
                       gldf(p, i + 2, cap), gldf(p, i + 3, cap));
}
__device__ __forceinline__ void gst2(float* p, long long i, long long cap, float2 v) {
    if (i >= 0 && i + 1 < cap && ((i & 1) == 0)) { *(float2*)(p + i) = v; return; }
    if (i >= 0     && i     < cap) p[i]     = v.x;
    if (i + 1 >= 0 && i + 1 < cap) p[i + 1] = v.y;
}
__device__ __forceinline__ float2 cmul(float2 a, float2 b) {
    return make_float2(fmaf(a.x, b.x, -a.y * b.y), fmaf(a.x, b.y, a.y * b.x));
}
__device__ __forceinline__ float2 crecip(float2 a) {
    float inv = 1.0f / fmaf(a.x, a.x, a.y * a.y);
    return make_float2(a.x * inv, -a.y * inv);
}
__device__ __forceinline__ float2 wred2(float2 v) {
    #pragma unroll
    for (int o = 16; o; o >>= 1) {
        v.x += __shfl_xor_sync(0xffffffffu, v.x, o);
        v.y += __shfl_xor_sync(0xffffffffu, v.y, o);
    }
    return v;
}

// ---- K1: masked PSD (upper triangle) + mask sums. block=(bf, rq) 64 thr ----
// v2: y-rows loaded inside the e-loop (one float4 pair live) to cut registers.
template<int RQ>
__device__ __forceinline__ void k1_body(
    int bf, int half, int lane,
    const float* __restrict__ re, const float* __restrict__ im,
    const float* __restrict__ ms, const float* __restrict__ mn,
    long long caps, long long capm)
{
    constexpr int R1 = 7 - RQ;
    const int b = bf >> 9, f = bf & 511;
    const long long mb = (long long)bf * T_;
    const long long base0 = ((long long)(b * C_) * F_ + f) * T_;

    float2 a0S[8], a0N[8], a1S[8], a1N[8];
    #pragma unroll
    for (int e = RQ; e < 8; e++) { a0S[e] = make_float2(0.f, 0.f); a0N[e] = a0S[e]; }
    #pragma unroll
    for (int e = R1; e < 8; e++) { a1S[e] = make_float2(0.f, 0.f); a1N[e] = a1S[e]; }
    float ss = 0.f, sn = 0.f;

    const int i4beg = half * (T_ / 8) + lane;
    const int i4end = half ? (T_ / 4) : (T_ / 8);
    for (int i4 = i4beg; i4 < i4end; i4 += 32) {
        const int t = i4 * 4;
        float4 mS4 = gld4(ms, mb + t, capm);
        float4 mN4 = gld4(mn, mb + t, capm);
        if (RQ == 3) {
            ss += (mS4.x + mS4.y) + (mS4.z + mS4.w);
            sn += (mN4.x + mN4.y) + (mN4.z + mN4.w);
        }
        // preload only the two x-rows
        float4 x0r = gld4(re, base0 + RQ * ROWSTRIDE + t, caps);
        float4 x0i = gld4(im, base0 + RQ * ROWSTRIDE + t, caps);
        float4 x1r = gld4(re, base0 + R1 * ROWSTRIDE + t, caps);
        float4 x1i = gld4(im, base0 + R1 * ROWSTRIDE + t, caps);

        const float* mSa = &mS4.x; const float* mNa = &mN4.x;
        #pragma unroll
        for (int e = RQ; e < 8; e++) {
            float4 yr4 = gld4(re, base0 + e * ROWSTRIDE + t, caps);
            float4 yi4 = gld4(im, base0 + e * ROWSTRIDE + t, caps);
            #pragma unroll
            for (int j = 0; j < 4; j++) {
                const float mS = mSa[j], mN = mNa[j];
                const float yre = (&yr4.x)[j], yie = (&yi4.x)[j];
                {   // row RQ vs e
                    const float xr0 = (&x0r.x)[j], xi0 = (&x0i.x)[j];
                    const float cr = fmaf(xr0, yre,  xi0 * yie);   // x*conj(y)
                    const float ci = fmaf(xi0, yre, -xr0 * yie);
                    a0S[e].x = fmaf(mS, cr, a0S[e].x);
                    a0S[e].y = fmaf(mS, ci, a0S[e].y);
                    a0N[e].x = fmaf(mN, cr, a0N[e].x);
                    a0N[e].y = fmaf(mN, ci, a0N[e].y);
                }
                if (e >= R1) {   // row R1 vs e
                    const float xr1 = (&x1r.x)[j], xi1 = (&x1i.x)[j];
                    const float cr = fmaf(xr1, yre,  xi1 * yie);
                    const float ci = fmaf(xi1, yre, -xr1 * yie);
                    a1S[e].x = fmaf(mS, cr, a1S[e].x);
                    a1S[e].y = fmaf(mS, ci, a1S[e].y);
                    a1N[e].x = fmaf(mN, cr, a1N[e].x);
                    a1N[e].y = fmaf(mN, ci, a1N[e].y);
                }
            }
        }
    }

    // warp-reduce; lane 0 writes tiny partials: [bf][p][q][half]
    #pragma unroll
    for (int e = RQ; e < 8; e++) {
        float2 vS = wred2(a0S[e]);
        float2 vN = wred2(a0N[e]);
        if (lane == 0) {
            size_t base = ((size_t)bf * 36 + IDX(RQ, e)) * 8 + half;
            d_part2[base + 0] = vS.x;
            d_part2[base + 2] = vS.y;
            d_part2[base + 4] = vN.x;
            d_part2[base + 6] = vN.y;
        }
    }
    #pragma unroll
    for (int e = R1; e < 8; e++) {
        float2 vS = wred2(a1S[e]);
        float2 vN = wred2(a1N[e]);
        if (lane == 0) {
            size_t base = ((size_t)bf * 36 + IDX(R1, e)) * 8 + half;
            d_part2[base + 0] = vS.x;
            d_part2[base + 2] = vS.y;
            d_part2[base + 4] = vN.x;
            d_part2[base + 6] = vN.y;
        }
    }
    if (RQ == 3) {
        float2 m2 = wred2(make_float2(ss, sn));
        if (lane == 0) {
            d_msum[bf * 4 + half * 2 + 0] = m2.x;
            d_msum[bf * 4 + half * 2 + 1] = m2.y;
        }
    }
}

__global__ void __launch_bounds__(64)
k1(const float* __restrict__ re, const float* __restrict__ im,
   const float* __restrict__ ms, const float* __restrict__ mn,
   long long caps, long long capm) {
    const int bf   = blockIdx.x;
    const int rq   = blockIdx.y;
    const int half = threadIdx.x >> 5;
    const int lane = threadIdx.x & 31;
    switch (rq) {
        case 0: k1_body<0>(bf, half, lane, re, im, ms, mn, caps, capm); break;
        case 1: k1_body<1>(bf, half, lane, re, im, ms, mn, caps, capm); break;
        case 2: k1_body<2>(bf, half, lane, re, im, ms, mn, caps, capm); break;
        default: k1_body<3>(bf, half, lane, re, im, ms, mn, caps, capm); break;
    }
}

// ---- KS: solve only (proven, unchanged). one warp per (b,f) ----
__global__ void __launch_bounds__(256)
kS() {
    const int w    = blockIdx.x * 8 + (threadIdx.x >> 5);   // bf
    const int lane = threadIdx.x & 31;

    const float invS = 1.0f / (d_msum[w * 4 + 0] + d_msum[w * 4 + 2] + 1e-10f);
    const float invN = 1.0f / (d_msum[w * 4 + 1] + d_msum[w * 4 + 3] + 1e-10f);

    const float* P = d_part2 + (size_t)w * 288;   // [p][q][half]

    float trN = 0.f;
    #pragma unroll
    for (int i = 0; i < 8; i++) {
        const float* q = P + IDX(i, i) * 8;
        trN += q[4] + q[5];
    }
    trN *= invN;
    const float dreg = 1e-6f * trN + 1e-8f;

    const int jc  = lane & 7;
    const int isB = (lane >> 3) & 1;
    const float sc = isB ? invS : invN;
    const int qo = isB ? 0 : 4;

    float2 col[8];
    #pragma unroll
    for (int i = 0; i < 8; i++) {
        const int r = i < jc ? i : jc;
        const int e = i < jc ? jc : i;
        const float* q = P + IDX(r, e) * 8 + qo;
        float vr = (q[0] + q[1]) * sc;
        float vi = (q[2] + q[3]) * sc;
        if (i > jc) vi = -vi;                 // Hermitian reconstruction
        col[i] = make_float2(vr, vi);
        if (!isB && i == jc) col[i].x += dreg;
    }

    #pragma unroll
    for (int k = 0; k < 8; k++) {
        float2 piv;
        piv.x = __shfl_sync(0xffffffffu, col[k].x, k);
        piv.y = __shfl_sync(0xffffffffu, col[k].y, k);
        float2 pinv = crecip(piv);
        col[k] = cmul(col[k], pinv);
        #pragma unroll
        for (int i = 0; i < 8; i++) {
            if (i == k) continue;
            float2 fct;
            fct.x = __shfl_sync(0xffffffffu, col[i].x, k);
            fct.y = __shfl_sync(0xffffffffu, col[i].y, k);
            float2 t2 = cmul(fct, col[k]);
            col[i].x -= t2.x; col[i].y -= t2.y;
        }
    }

    float2 dg = make_float2(0.f, 0.f);
    #pragma unroll
    for (int i = 0; i < 8; i++)
        if (lane == 8 + i) dg = col[i];
    dg = wred2(dg);
    float2 cd = make_float2(1.0f + dg.x, -dg.y);   // conj(beta + tr(X))
    float2 E  = crecip(cd);

    if (lane >= 8 && lane < 16) {
        const int m = lane - 8;
        float2* Gp = (float2*)(d_G + (size_t)w * 128) + m * 8;
        #pragma unroll
        for (int c = 0; c < 8; c++) {
            float2 xc = make_float2(col[c].x, -col[c].y);
            Gp[c] = cmul(xc, E);
        }
    }
}

// ---- K2: apply. block per (b,f); G in smem; thread per 2t; 64-bit ld/st ----
__global__ void __launch_bounds__(256)
k2(const float* __restrict__ re, const float* __restrict__ im,
   float* __restrict__ outf, long long caps, long long capoutf)
{
    __shared__ float2 sG[64];
    const int bf  = blockIdx.x;
    const int b   = bf >> 9, f = bf & 511;
    const int tid = threadIdx.x;

    if (tid < 64)
        sG[tid] = *((const float2*)(d_G + (size_t)bf * 128) + tid);
    __syncthreads();

    long long xb[8];
    #pragma unroll
    for (int c = 0; c < 8; c++)
        xb[c] = ((long long)(b * C_ + c) * F_ + f) * T_;

    for (int u = tid; u < T_ / 2; u += 256) {
        const int t = u * 2;
        float2 xr[8], xi[8];   // (t0, t1) per channel
        #pragma unroll
        for (int c = 0; c < 8; c++) {
            xr[c] = gld2(re, xb[c] + t, caps);
            xi[c] = gld2(im, xb[c] + t, caps);
        }
        #pragma unroll
        for (int m = 0; m < 8; m++) {
            float ar0 = 0.f, ai0 = 0.f, ar1 = 0.f, ai1 = 0.f;
            #pragma unroll
            for (int c = 0; c < 8; c++) {
                const float2 g = sG[m * 8 + c];     // one LDS, both t
                ar0 = fmaf(g.x, xr[c].x, ar0);
                ar0 = fmaf(-g.y, xi[c].x, ar0);
                ai0 = fmaf(g.x, xi[c].x, ai0);
                ai0 = fmaf(g.y, xr[c].x, ai0);
                ar1 = fmaf(g.x, xr[c].y, ar1);
                ar1 = fmaf(-g.y, xi[c].y, ar1);
                ai1 = fmaf(g.x, xi[c].y, ai1);
                ai1 = fmaf(g.y, xr[c].y, ai1);
            }
            const long long oc = xb[m] + t;
            gst2(outf, oc,          capoutf, make_float2(ar0, ar1));  // real plane
            gst2(outf, SPEC_N + oc, capoutf, make_float2(ai0, ai1));  // imag plane
        }
    }
}

extern "C" void kernel_launch(void* const* d_in, const int* in_sizes, int n_in,
                              void* d_out, int out_size) {
    if (n_in < 4 || !d_out) return;

    const float* re  = (const float*)d_in[0];
    const float* im  = (const float*)d_in[1];
    const float* mks = (const float*)d_in[2];
    const float* mkn = (const float*)d_in[3];
    long long cap_re = (long long)in_sizes[0];
    long long cap_im = (long long)in_sizes[1];
    long long caps   = cap_re < cap_im ? cap_re : cap_im;
    long long cm0 = (long long)in_sizes[2];
    long long cm1 = (long long)in_sizes[3];
    long long capm = cm0 < cm1 ? cm0 : cm1;
    long long capoutf = (long long)out_size;   // float32 element count (confirmed)

    k1<<<dim3(NBF, 4), 64>>>(re, im, mks, mkn, caps, capm);
    kS<<<NBF / 8, 256>>>();
    k2<<<NBF, 256>>>(re, im, (float*)d_out, caps, capoutf);
}

// round 17
// speedup vs baseline: 1.6399x; 1.1512x over previous
#include <cuda_runtime.h>

#define B_ 4
#define C_ 8
#define F_ 512
#define T_ 1000

#define SPEC_N 16384000ll   // B*C*F*T
#define NBF    2048         // B*F

// triangle pair index for r <= e
#define IDX(r, e) ((r) * 8 + (e) - ((r) * ((r) + 1)) / 2)   // 0..35

// -------- device scratch --------
// reduced PSD partials: [bf][p36][q4][half2]  q: 0=S.re 1=S.im 2=N.re 3=N.im
__device__ __align__(16) float d_part2[(size_t)NBF * 288];
__device__ float d_msum[NBF * 4];                       // [bf][half][s/n]
__device__ __align__(16) float d_G[(size_t)NBF * 128];  // [bf][m][c][2] : conj(W[c][m])

// ---------------- helpers ----------------
__device__ __forceinline__ float gldf(const float* p, long long i, long long cap) {
    return (i >= 0 && i < cap) ? p[i] : 0.0f;
}
__device__ __forceinline__ float2 gld2(const float* p, long long i, long long cap) {
    if (i >= 0 && i + 1 < cap && ((i & 1) == 0))
        return *(const float2*)(p + i);
    return make_float2(gldf(p, i, cap), gldf(p, i + 1, cap));
}
__device__ __forceinline__ float4 gld4(const float* p, long long i, long long cap) {
    if (i >= 0 && i + 3 < cap && ((i & 3) == 0))
        return *(const float4*)(p + i);
    return make_float4(gldf(p, i, cap), gldf(p, i + 1, cap),
                       gldf(p, i + 2, cap), gldf(p, i + 3, cap));
}
__device__ __forceinline__ void gst2(float* p, long long i, long long cap, float2 v) {
    if (i >= 0 && i + 1 < cap && ((i & 1) == 0)) { *(float2*)(p + i) = v; return; }
    if (i >= 0     && i     < cap) p[i]     = v.x;
    if (i + 1 >= 0 && i + 1 < cap) p[i + 1] = v.y;
}
__device__ __forceinline__ float2 cmul(float2 a, float2 b) {
    return make_float2(fmaf(a.x, b.x, -a.y * b.y), fmaf(a.x, b.y, a.y * b.x));
}
__device__ __forceinline__ float2 crecip(float2 a) {
    float inv = 1.0f / fmaf(a.x, a.x, a.y * a.y);
    return make_float2(a.x * inv, -a.y * inv);
}
__device__ __forceinline__ float2 wred2(float2 v) {
    #pragma unroll
    for (int o = 16; o; o >>= 1) {
        v.x += __shfl_xor_sync(0xffffffffu, v.x, o);
        v.y += __shfl_xor_sync(0xffffffffu, v.y, o);
    }
    return v;
}

// ---- K1: masked PSD (upper triangle) + mask sums. block=(bf, rq) 64 thr ----
// R11 version: y-rows front-batched (max MLP) — proven 102 us.
template<int RQ>
__device__ __forceinline__ void k1_body(
    int bf, int half, int lane,
    const float* __restrict__ re, const float* __restrict__ im,
    const float* __restrict__ ms, const float* __restrict__ mn,
    long long caps, long long capm)
{
    constexpr int R1 = 7 - RQ;
    const int b = bf >> 9, f = bf & 511;
    const long long mb = (long long)bf * T_;
    long long xb[8];
    #pragma unroll
    for (int q = RQ; q < 8; q++)
        xb[q] = ((long long)(b * C_ + q) * F_ + f) * T_;

    float2 a0S[8], a0N[8], a1S[8], a1N[8];
    #pragma unroll
    for (int e = RQ; e < 8; e++) { a0S[e] = make_float2(0.f, 0.f); a0N[e] = a0S[e]; }
    #pragma unroll
    for (int e = R1; e < 8; e++) { a1S[e] = make_float2(0.f, 0.f); a1N[e] = a1S[e]; }
    float ss = 0.f, sn = 0.f;

    const int i4beg = half * (T_ / 8) + lane;
    const int i4end = half ? (T_ / 4) : (T_ / 8);
    for (int i4 = i4beg; i4 < i4end; i4 += 32) {
        const int t = i4 * 4;
        float4 mS4 = gld4(ms, mb + t, capm);
        float4 mN4 = gld4(mn, mb + t, capm);
        if (RQ == 3) {
            ss += (mS4.x + mS4.y) + (mS4.z + mS4.w);
            sn += (mN4.x + mN4.y) + (mN4.z + mN4.w);
        }
        float4 yr[8], yi[8];
        #pragma unroll
        for (int q = RQ; q < 8; q++) {
            yr[q] = gld4(re, xb[q] + t, caps);
            yi[q] = gld4(im, xb[q] + t, caps);
        }
        const float* mSa = &mS4.x; const float* mNa = &mN4.x;
        #pragma unroll
        for (int j = 0; j < 4; j++) {
            float mS = mSa[j], mN = mNa[j];
            {   // row RQ vs e = RQ..7
                float xr0 = (&yr[RQ].x)[j], xi0 = (&yi[RQ].x)[j];
                #pragma unroll
                for (int e = RQ; e < 8; e++) {
                    float yre = (&yr[e].x)[j], yie = (&yi[e].x)[j];
                    float cr = fmaf(xr0, yre,  xi0 * yie);   // x*conj(y)
                    float ci = fmaf(xi0, yre, -xr0 * yie);
                    a0S[e].x = fmaf(mS, cr, a0S[e].x);
                    a0S[e].y = fmaf(mS, ci, a0S[e].y);
                    a0N[e].x = fmaf(mN, cr, a0N[e].x);
                    a0N[e].y = fmaf(mN, ci, a0N[e].y);
                }
            }
            {   // row R1 vs e = R1..7
                float xr1 = (&yr[R1].x)[j], xi1 = (&yi[R1].x)[j];
                #pragma unroll
                for (int e = R1; e < 8; e++) {
                    float yre = (&yr[e].x)[j], yie = (&yi[e].x)[j];
                    float cr = fmaf(xr1, yre,  xi1 * yie);
                    float ci = fmaf(xi1, yre, -xr1 * yie);
                    a1S[e].x = fmaf(mS, cr, a1S[e].x);
                    a1S[e].y = fmaf(mS, ci, a1S[e].y);
                    a1N[e].x = fmaf(mN, cr, a1N[e].x);
                    a1N[e].y = fmaf(mN, ci, a1N[e].y);
                }
            }
        }
    }

    // warp-reduce; lane 0 writes tiny partials: [bf][p][q][half]
    #pragma unroll
    for (int e = RQ; e < 8; e++) {
        float2 vS = wred2(a0S[e]);
        float2 vN = wred2(a0N[e]);
        if (lane == 0) {
            size_t base = ((size_t)bf * 36 + IDX(RQ, e)) * 8 + half;
            d_part2[base + 0] = vS.x;
            d_part2[base + 2] = vS.y;
            d_part2[base + 4] = vN.x;
            d_part2[base + 6] = vN.y;
        }
    }
    #pragma unroll
    for (int e = R1; e < 8; e++) {
        float2 vS = wred2(a1S[e]);
        float2 vN = wred2(a1N[e]);
        if (lane == 0) {
            size_t base = ((size_t)bf * 36 + IDX(R1, e)) * 8 + half;
            d_part2[base + 0] = vS.x;
            d_part2[base + 2] = vS.y;
            d_part2[base + 4] = vN.x;
            d_part2[base + 6] = vN.y;
        }
    }
    if (RQ == 3) {
        float2 m2 = wred2(make_float2(ss, sn));
        if (lane == 0) {
            d_msum[bf * 4 + half * 2 + 0] = m2.x;
            d_msum[bf * 4 + half * 2 + 1] = m2.y;
        }
    }
}

__global__ void __launch_bounds__(64)
k1(const float* __restrict__ re, const float* __restrict__ im,
   const float* __restrict__ ms, const float* __restrict__ mn,
   long long caps, long long capm) {
    const int bf   = blockIdx.x;
    const int rq   = blockIdx.y;
    const int half = threadIdx.x >> 5;
    const int lane = threadIdx.x & 31;
    switch (rq) {
        case 0: k1_body<0>(bf, half, lane, re, im, ms, mn, caps, capm); break;
        case 1: k1_body<1>(bf, half, lane, re, im, ms, mn, caps, capm); break;
        case 2: k1_body<2>(bf, half, lane, re, im, ms, mn, caps, capm); break;
        default: k1_body<3>(bf, half, lane, re, im, ms, mn, caps, capm); break;
    }
}

// ---- KS: solve only (proven, unchanged). one warp per (b,f) ----
__global__ void __launch_bounds__(256)
kS() {
    const int w    = blockIdx.x * 8 + (threadIdx.x >> 5);   // bf
    const int lane = threadIdx.x & 31;

    const float invS = 1.0f / (d_msum[w * 4 + 0] + d_msum[w * 4 + 2] + 1e-10f);
    const float invN = 1.0f / (d_msum[w * 4 + 1] + d_msum[w * 4 + 3] + 1e-10f);

    const float* P = d_part2 + (size_t)w * 288;   // [p][q][half]

    float trN = 0.f;
    #pragma unroll
    for (int i = 0; i < 8; i++) {
        const float* q = P + IDX(i, i) * 8;
        trN += q[4] + q[5];
    }
    trN *= invN;
    const float dreg = 1e-6f * trN + 1e-8f;

    const int jc  = lane & 7;
    const int isB = (lane >> 3) & 1;
    const float sc = isB ? invS : invN;
    const int qo = isB ? 0 : 4;

    float2 col[8];
    #pragma unroll
    for (int i = 0; i < 8; i++) {
        const int r = i < jc ? i : jc;
        const int e = i < jc ? jc : i;
        const float* q = P + IDX(r, e) * 8 + qo;
        float vr = (q[0] + q[1]) * sc;
        float vi = (q[2] + q[3]) * sc;
        if (i > jc) vi = -vi;                 // Hermitian reconstruction
        col[i] = make_float2(vr, vi);
        if (!isB && i == jc) col[i].x += dreg;
    }

    #pragma unroll
    for (int k = 0; k < 8; k++) {
        float2 piv;
        piv.x = __shfl_sync(0xffffffffu, col[k].x, k);
        piv.y = __shfl_sync(0xffffffffu, col[k].y, k);
        float2 pinv = crecip(piv);
        col[k] = cmul(col[k], pinv);
        #pragma unroll
        for (int i = 0; i < 8; i++) {
            if (i == k) continue;
            float2 fct;
            fct.x = __shfl_sync(0xffffffffu, col[i].x, k);
            fct.y = __shfl_sync(0xffffffffu, col[i].y, k);
            float2 t2 = cmul(fct, col[k]);
            col[i].x -= t2.x; col[i].y -= t2.y;
        }
    }

    float2 dg = make_float2(0.f, 0.f);
    #pragma unroll
    for (int i = 0; i < 8; i++)
        if (lane == 8 + i) dg = col[i];
    dg = wred2(dg);
    float2 cd = make_float2(1.0f + dg.x, -dg.y);   // conj(beta + tr(X))
    float2 E  = crecip(cd);

    if (lane >= 8 && lane < 16) {
        const int m = lane - 8;
        float2* Gp = (float2*)(d_G + (size_t)w * 128) + m * 8;
        #pragma unroll
        for (int c = 0; c < 8; c++) {
            float2 xc = make_float2(col[c].x, -col[c].y);
            Gp[c] = cmul(xc, E);
        }
    }
}

// ---- K2: apply (R16-proven). block per (b,f); G in smem; thread per 2t ----
__global__ void __launch_bounds__(256)
k2(const float* __restrict__ re, const float* __restrict__ im,
   float* __restrict__ outf, long long caps, long long capoutf)
{
    __shared__ float2 sG[64];
    const int bf  = blockIdx.x;
    const int b   = bf >> 9, f = bf & 511;
    const int tid = threadIdx.x;

    if (tid < 64)
        sG[tid] = *((const float2*)(d_G + (size_t)bf * 128) + tid);
    __syncthreads();

    long long xb[8];
    #pragma unroll
    for (int c = 0; c < 8; c++)
        xb[c] = ((long long)(b * C_ + c) * F_ + f) * T_;

    for (int u = tid; u < T_ / 2; u += 256) {
        const int t = u * 2;
        float2 xr[8], xi[8];   // (t0, t1) per channel
        #pragma unroll
        for (int c = 0; c < 8; c++) {
            xr[c] = gld2(re, xb[c] + t, caps);
            xi[c] = gld2(im, xb[c] + t, caps);
        }
        #pragma unroll
        for (int m = 0; m < 8; m++) {
            float ar0 = 0.f, ai0 = 0.f, ar1 = 0.f, ai1 = 0.f;
            #pragma unroll
            for (int c = 0; c < 8; c++) {
                const float2 g = sG[m * 8 + c];     // one LDS, both t
                ar0 = fmaf(g.x, xr[c].x, ar0);
                ar0 = fmaf(-g.y, xi[c].x, ar0);
                ai0 = fmaf(g.x, xi[c].x, ai0);
                ai0 = fmaf(g.y, xr[c].x, ai0);
                ar1 = fmaf(g.x, xr[c].y, ar1);
                ar1 = fmaf(-g.y, xi[c].y, ar1);
                ai1 = fmaf(g.x, xi[c].y, ai1);
                ai1 = fmaf(g.y, xr[c].y, ai1);
            }
            const long long oc = xb[m] + t;
            gst2(outf, oc,          capoutf, make_float2(ar0, ar1));  // real plane
            gst2(outf, SPEC_N + oc, capoutf, make_float2(ai0, ai1));  // imag plane
        }
    }
}

extern "C" void kernel_launch(void* const* d_in, const int* in_sizes, int n_in,
                              void* d_out, int out_size) {
    if (n_in < 4 || !d_out) return;

    const float* re  = (const float*)d_in[0];
    const float* im  = (const float*)d_in[1];
    const float* mks = (const float*)d_in[2];
    const float* mkn = (const float*)d_in[3];
    long long cap_re = (long long)in_sizes[0];
    long long cap_im = (long long)in_sizes[1];
    long long caps   = cap_re < cap_im ? cap_re : cap_im;
    long long cm0 = (long long)in_sizes[2];
    long long cm1 = (long long)in_sizes[3];
    long long capm = cm0 < cm1 ? cm0 : cm1;
    long long capoutf = (long long)out_size;   // float32 element count (confirmed)

    k1<<<dim3(NBF, 4), 64>>>(re, im, mks, mkn, caps, capm);
    kS<<<NBF / 8, 256>>>();
    k2<<<NBF, 256>>>(re, im, (float*)d_out, caps, capoutf);
}